// round 1
// baseline (speedup 1.0000x reference)
#include <cuda_runtime.h>
#include <cstdint>

#define D       256
#define BM      128
#define BN      128
#define BK      16
#define ZS      132   // padded stride for z_s [d][r]
#define ES      132   // padded stride for e_s [dk][n]
#define NTHREADS 256
#define NCHUNK  (D / BK)   // 16

__device__ float g_esq_half[8192];   // 0.5 * ||e_k||^2
__device__ float g_partial[512];     // per-block loss partials (deterministic)

// ---------------------------------------------------------------------------
// 0.5 * row-wise squared norms of codebook. One warp per row.
// ---------------------------------------------------------------------------
__global__ void esq_kernel(const float* __restrict__ cb, int K) {
    int row  = blockIdx.x * 8 + (threadIdx.x >> 5);
    if (row >= K) return;
    int lane = threadIdx.x & 31;
    const float4* p = reinterpret_cast<const float4*>(cb + (size_t)row * D);
    float s = 0.f;
#pragma unroll
    for (int i = 0; i < 2; i++) {
        float4 v = p[lane + 32 * i];
        s += v.x * v.x + v.y * v.y + v.z * v.z + v.w * v.w;
    }
#pragma unroll
    for (int o = 16; o; o >>= 1) s += __shfl_down_sync(0xffffffffu, s, o);
    if (lane == 0) g_esq_half[row] = 0.5f * s;
}

// ---------------------------------------------------------------------------
// Fused GEMM + argmin + gather + loss-partial. One block = 128 z rows.
// score[b][k] = 0.5*||e_k||^2 - z_b . e_k   (argmin-equivalent to d2)
// ---------------------------------------------------------------------------
__global__ __launch_bounds__(NTHREADS, 1)
void vq_main(const float* __restrict__ z_e, const float* __restrict__ cb,
             float* __restrict__ out, int B, int K, long long out_size) {
    extern __shared__ float smem[];
    float* z_s   = smem;                       // D * ZS
    float* e_s   = z_s + D * ZS;               // 2 * BK * ES (double buffer)
    float* esq_s = e_s + 2 * BK * ES;          // BN
    int*   row_i = (int*)(esq_s + BN);         // BM
    // reduction arrays alias e_s (used only after the tile loop)
    float* red_v = e_s;                        // BM*16
    int*   red_i = (int*)(e_s + BM * 16);      // BM*16

    const int tid  = threadIdx.x;
    const int row0 = blockIdx.x * BM;
    const int tr   = tid >> 4;   // 0..15 : row group
    const int tc   = tid & 15;   // 0..15 : col group

    // ---- load z tile, transposed: z_s[d][r] ----
    for (int i = tid; i < BM * D; i += NTHREADS) {
        int r = i >> 8;        // i / 256
        int d = i & 255;       // i % 256
        z_s[d * ZS + r] = z_e[(size_t)(row0 + r) * D + d];
    }
    __syncthreads();

    float bestv[8];
    int   besti[8];
#pragma unroll
    for (int i = 0; i < 8; i++) { bestv[i] = 3.4e38f; besti[i] = 0; }

    const int NTILE = K / BN;
    for (int nt = 0; nt < NTILE; nt++) {
        const int n0 = nt * BN;

        // tile prologue: esq slice + chunk 0 into buffer 0
        if (tid < BN) esq_s[tid] = g_esq_half[n0 + tid];
        {
#pragma unroll
            for (int jj = 0; jj < 2; jj++) {
                int ff  = tid + 256 * jj;   // float4 index (512 total)
                int n   = ff >> 2;
                int dk4 = ff & 3;
                float4 v = reinterpret_cast<const float4*>(
                    cb + (size_t)(n0 + n) * D)[dk4];
                float* dst = e_s + (dk4 * 4) * ES + n;
                dst[0 * ES] = v.x; dst[1 * ES] = v.y;
                dst[2 * ES] = v.z; dst[3 * ES] = v.w;
            }
        }
        __syncthreads();

        float esq_r[8];
#pragma unroll
        for (int j = 0; j < 8; j++) esq_r[j] = esq_s[tc * 8 + j];

        float acc[8][8];
#pragma unroll
        for (int i = 0; i < 8; i++)
#pragma unroll
            for (int j = 0; j < 8; j++) acc[i][j] = 0.f;

        int buf = 0;
        for (int c = 0; c < NCHUNK; c++) {
            float4 ld[2];
            if (c + 1 < NCHUNK) {
#pragma unroll
                for (int jj = 0; jj < 2; jj++) {
                    int ff  = tid + 256 * jj;
                    int n   = ff >> 2;
                    int dk4 = ff & 3;
                    ld[jj] = reinterpret_cast<const float4*>(
                        cb + (size_t)(n0 + n) * D + (c + 1) * BK)[dk4];
                }
            }
            const float* eb = e_s + buf * BK * ES;
            const float* zb = z_s + (c * BK) * ZS;
#pragma unroll
            for (int kk = 0; kk < BK; kk++) {
                float4 a0 = *(const float4*)&zb[kk * ZS + tr * 8];
                float4 a1 = *(const float4*)&zb[kk * ZS + tr * 8 + 4];
                float4 b0 = *(const float4*)&eb[kk * ES + tc * 8];
                float4 b1 = *(const float4*)&eb[kk * ES + tc * 8 + 4];
                float az[8] = {a0.x, a0.y, a0.z, a0.w, a1.x, a1.y, a1.z, a1.w};
                float bz[8] = {b0.x, b0.y, b0.z, b0.w, b1.x, b1.y, b1.z, b1.w};
#pragma unroll
                for (int i = 0; i < 8; i++)
#pragma unroll
                    for (int j = 0; j < 8; j++)
                        acc[i][j] = fmaf(az[i], bz[j], acc[i][j]);
            }
            if (c + 1 < NCHUNK) {
#pragma unroll
                for (int jj = 0; jj < 2; jj++) {
                    int ff  = tid + 256 * jj;
                    int n   = ff >> 2;
                    int dk4 = ff & 3;
                    float* dst = e_s + (buf ^ 1) * BK * ES + (dk4 * 4) * ES + n;
                    dst[0 * ES] = ld[jj].x; dst[1 * ES] = ld[jj].y;
                    dst[2 * ES] = ld[jj].z; dst[3 * ES] = ld[jj].w;
                }
            }
            __syncthreads();
            buf ^= 1;
        }

        // argmin update: score = 0.5||e||^2 - dot
#pragma unroll
        for (int i = 0; i < 8; i++) {
#pragma unroll
            for (int j = 0; j < 8; j++) {
                float s = esq_r[j] - acc[i][j];
                int idx = n0 + tc * 8 + j;
                if (s < bestv[i]) { bestv[i] = s; besti[i] = idx; }
            }
        }
        __syncthreads();   // before next tile's prologue overwrites e_s/esq_s
    }

    // ---- cross-thread argmin reduction (16 col-groups per row) ----
#pragma unroll
    for (int i = 0; i < 8; i++) {
        red_v[(tr * 8 + i) * 16 + tc] = bestv[i];
        red_i[(tr * 8 + i) * 16 + tc] = besti[i];
    }
    __syncthreads();

    if (tid < BM) {
        float bv = red_v[tid * 16];
        int   bi = red_i[tid * 16];
#pragma unroll
        for (int t = 1; t < 16; t++) {
            float v  = red_v[tid * 16 + t];
            int   ii = red_i[tid * 16 + t];
            if (v < bv || (v == bv && ii < bi)) { bv = v; bi = ii; }
        }
        row_i[tid] = bi;
        long long pos = (long long)B * D + row0 + tid;   // indices block
        if (pos < out_size) out[pos] = (float)bi;
    }
    __syncthreads();

    // ---- gather z_q, write z_q_st = z_e + (z_q - z_e), accumulate loss ----
    float lsum = 0.f;
    for (int r = 0; r < BM; r++) {
        int idx  = row_i[r];
        float zq = cb[(size_t)idx * D + tid];
        float ze = z_s[tid * ZS + r];
        float diff = zq - ze;
        long long pos = (long long)(row0 + r) * D + tid;
        if (pos < out_size) out[pos] = ze + diff;   // matches reference expr
        lsum += diff * diff;
    }

    // deterministic block reduction of loss partial
    __syncthreads();
    red_v[tid] = lsum;
    __syncthreads();
#pragma unroll
    for (int s = 128; s > 0; s >>= 1) {
        if (tid < s) red_v[tid] += red_v[tid + s];
        __syncthreads();
    }
    if (tid == 0) g_partial[blockIdx.x] = red_v[0];
}

// ---------------------------------------------------------------------------
// Final: deterministic fixed-order sum of partials -> vq_loss
// vq_loss = (1 + 0.25) * mean((z_q - z_e)^2)
// ---------------------------------------------------------------------------
__global__ void final_kernel(float* __restrict__ out, int B, int nblocks,
                             long long out_size) {
    if (threadIdx.x == 0 && blockIdx.x == 0) {
        float s = 0.f;
        for (int i = 0; i < nblocks; i++) s += g_partial[i];
        float mse = s / ((float)B * (float)D);
        long long pos = (long long)B * D + B;
        if (pos < out_size) out[pos] = 1.25f * mse;
    }
}

// ---------------------------------------------------------------------------
extern "C" void kernel_launch(void* const* d_in, const int* in_sizes, int n_in,
                              void* d_out, int out_size) {
    const float* z_e = (const float*)d_in[0];
    const float* cb  = (const float*)d_in[1];
    float* out       = (float*)d_out;

    int B = in_sizes[0] / D;   // 32768
    int K = in_sizes[1] / D;   // 8192

    esq_kernel<<<(K + 7) / 8, NTHREADS>>>(cb, K);

    size_t smem_bytes = (size_t)(D * ZS + 2 * BK * ES + BN) * sizeof(float)
                        + BM * sizeof(int);
    cudaFuncSetAttribute(vq_main, cudaFuncAttributeMaxDynamicSharedMemorySize,
                         (int)smem_bytes);
    vq_main<<<B / BM, NTHREADS, smem_bytes>>>(z_e, cb, out, B, K,
                                              (long long)out_size);

    final_kernel<<<1, 32>>>(out, B, B / BM, (long long)out_size);
}

// round 4
// speedup vs baseline: 2.6981x; 2.6981x over previous
#include <cuda_runtime.h>
#include <cuda_fp16.h>
#include <cstdint>

#define BROWS  32768
#define KROWS  8192
#define DDIM   256
#define TH1    0.10f
#define TH2    1e-3f
#define RCAP   16384
#define R2CAP  1024

// ---------------- device globals (no cudaMalloc allowed) --------------------
__device__ __align__(16) __half g_z_hi[BROWS * DDIM];
__device__ __align__(16) __half g_z_lo[BROWS * DDIM];
__device__ __align__(16) __half g_cb_hi[KROWS * DDIM];
__device__ __align__(16) __half g_cb_lo[KROWS * DDIM];
__device__ __align__(16) float g_esq[KROWS];     // 0.5*||e||^2 exact fp32
__device__ int   g_row_idx[BROWS];
__device__ int   g_nrisky;
__device__ int   g_risky[RCAP];
__device__ int   g_nr2;
__device__ int   g_r2[R2CAP];
__device__ float g_partial[BROWS / 128];

// ---------------- asm helpers (baseline PTX only) ----------------------------
__device__ __forceinline__ uint32_t smem_u32(const void* p) {
    uint32_t a;
    asm("{ .reg .u64 t; cvta.to.shared.u64 t, %1; cvt.u32.u64 %0, t; }"
        : "=r"(a) : "l"(p));
    return a;
}
__device__ __forceinline__ void ldmx4(uint32_t r[4], uint32_t addr) {
    asm volatile("ldmatrix.sync.aligned.m8n8.x4.shared.b16 {%0,%1,%2,%3}, [%4];\n"
        : "=r"(r[0]), "=r"(r[1]), "=r"(r[2]), "=r"(r[3]) : "r"(addr));
}
__device__ __forceinline__ void mma16816(float c[4], const uint32_t a[4],
                                         uint32_t b0, uint32_t b1) {
    asm volatile(
        "mma.sync.aligned.m16n8k16.row.col.f32.f16.f16.f32 "
        "{%0,%1,%2,%3}, {%4,%5,%6,%7}, {%8,%9}, {%0,%1,%2,%3};\n"
        : "+f"(c[0]), "+f"(c[1]), "+f"(c[2]), "+f"(c[3])
        : "r"(a[0]), "r"(a[1]), "r"(a[2]), "r"(a[3]), "r"(b0), "r"(b1));
}
__device__ __forceinline__ void cp16(uint32_t dst, const void* src) {
    asm volatile("cp.async.cg.shared.global [%0], [%1], 16;\n"
        :: "r"(dst), "l"(src));
}
#define CPC()  asm volatile("cp.async.commit_group;\n" ::: "memory")
#define CPW(n) asm volatile("cp.async.wait_group %0;\n" :: "n"(n) : "memory")

// merge (b,s,i) with (ob,os,oi); tie -> lower index
__device__ __forceinline__ void merge3(float& b, float& s, int& i,
                                       float ob, float os, int oi) {
    if (ob < b || (ob == b && oi < i)) {
        s = fminf(b, os); b = ob; i = oi;
    } else {
        s = fminf(s, ob);
    }
}

// ---------------- prep kernels ----------------------------------------------
__global__ void init_kernel() { g_nrisky = 0; g_nr2 = 0; }

__global__ void split_kernel(const float* __restrict__ src,
                             __half* __restrict__ hi,
                             __half* __restrict__ lo, int n4) {
    int i = blockIdx.x * blockDim.x + threadIdx.x;
    if (i >= n4) return;
    float4 v = reinterpret_cast<const float4*>(src)[i];
    __half h0 = __float2half(v.x), h1 = __float2half(v.y);
    __half h2 = __float2half(v.z), h3 = __float2half(v.w);
    __half2 hp0; hp0.x = h0; hp0.y = h1;
    __half2 hp1; hp1.x = h2; hp1.y = h3;
    __half2 lp0, lp1;
    lp0.x = __float2half(v.x - __half2float(h0));
    lp0.y = __float2half(v.y - __half2float(h1));
    lp1.x = __float2half(v.z - __half2float(h2));
    lp1.y = __float2half(v.w - __half2float(h3));
    reinterpret_cast<__half2*>(hi)[i * 2 + 0] = hp0;
    reinterpret_cast<__half2*>(hi)[i * 2 + 1] = hp1;
    reinterpret_cast<__half2*>(lo)[i * 2 + 0] = lp0;
    reinterpret_cast<__half2*>(lo)[i * 2 + 1] = lp1;
}

__global__ void esq_kernel(const float* __restrict__ cb) {
    int row = blockIdx.x * 8 + (threadIdx.x >> 5);
    if (row >= KROWS) return;
    int lane = threadIdx.x & 31;
    const float4* p = reinterpret_cast<const float4*>(cb + (size_t)row * DDIM);
    float s = 0.f;
#pragma unroll
    for (int i = 0; i < 2; i++) {
        float4 v = p[lane + 32 * i];
        s += v.x * v.x + v.y * v.y + v.z * v.z + v.w * v.w;
    }
#pragma unroll
    for (int o = 16; o; o >>= 1) s += __shfl_down_sync(0xffffffffu, s, o);
    if (lane == 0) g_esq[row] = 0.5f * s;
}

// ============================================================================
// Screen: fp16 HMMA GEMM + fused best/second argmin. 128 rows per CTA.
// SMEM: A 0..64K | B 64K..192K (2 x 64K) | esq 192K..224K
// ============================================================================
#define S_A 0u
#define S_B 65536u
#define S_E 196608u
#define SCR_SMEM 229376

__global__ __launch_bounds__(256, 1) void vq_screen() {
    extern __shared__ char sm[];
    const uint32_t sb = smem_u32(sm);
    float* esq_s = reinterpret_cast<float*>(sm + S_E);
    const int tid = threadIdx.x, lane = tid & 31, w = tid >> 5;
    const int wm = w & 3, wn = w >> 2;
    const int row0 = blockIdx.x * 128;

    // ---- prologue: A (z_hi rows), esq, B tile 0 -> group 0 ----
#pragma unroll
    for (int q = 0; q < 16; q++) {
        int lin = q * 256 + tid;
        int r = lin >> 5, c = lin & 31;
        cp16(sb + S_A + r * 512 + ((c * 16) ^ ((r & 7) << 4)),
             g_z_hi + (size_t)(row0 + r) * DDIM + c * 8);
    }
#pragma unroll
    for (int q = 0; q < 8; q++) {
        int c2 = q * 256 + tid;
        cp16(sb + S_E + c2 * 16, g_esq + c2 * 4);
    }
#pragma unroll
    for (int q = 0; q < 16; q++) {
        int lin = q * 256 + tid;
        int r = lin >> 5, c = lin & 31;
        cp16(sb + S_B + r * 512 + ((c * 16) ^ ((r & 7) << 4)),
             g_cb_hi + (size_t)r * DDIM + c * 8);
    }
    CPC();

    // ldmatrix address components
    const uint32_t aRow = (uint32_t)(wm * 32 + (lane & 15)) * 512;
    const uint32_t aK   = (uint32_t)((lane >> 4) * 16);
    const uint32_t aSw  = (uint32_t)((lane & 7) << 4);
    const uint32_t bRow = (uint32_t)(wn * 64 + (lane & 7) + ((lane >> 4) & 1) * 8) * 512;
    const uint32_t bK   = (uint32_t)(((lane >> 3) & 1) * 16);
    const uint32_t bSw  = aSw;

    float bestv[4], secv[4];
    int   besti[4];
#pragma unroll
    for (int s = 0; s < 4; s++) { bestv[s] = 3.4e38f; secv[s] = 3.4e38f; besti[s] = 0; }

    for (int t = 0; t < 64; t++) {
        if (t + 1 < 64) {
            const __half* src = g_cb_hi + (size_t)(t + 1) * 128 * DDIM;
            uint32_t dstB = sb + S_B + (uint32_t)((t + 1) & 1) * 65536;
#pragma unroll
            for (int q = 0; q < 16; q++) {
                int lin = q * 256 + tid;
                int r = lin >> 5, c = lin & 31;
                cp16(dstB + r * 512 + ((c * 16) ^ ((r & 7) << 4)),
                     src + (size_t)r * DDIM + c * 8);
            }
            CPC();
            CPW(1);
        } else {
            CPW(0);
        }
        __syncthreads();

        const uint32_t bufB = sb + S_B + (uint32_t)(t & 1) * 65536;
        float acc[2][8][4];
#pragma unroll
        for (int mf = 0; mf < 2; mf++)
#pragma unroll
            for (int nf = 0; nf < 8; nf++)
#pragma unroll
                for (int k = 0; k < 4; k++) acc[mf][nf][k] = 0.f;

#pragma unroll
        for (int ks = 0; ks < 16; ks++) {
            uint32_t a[2][4];
#pragma unroll
            for (int mf = 0; mf < 2; mf++)
                ldmx4(a[mf], sb + S_A + aRow + mf * 8192 +
                              (((uint32_t)(ks * 32) + aK) ^ aSw));
            uint32_t bb[4][4];
#pragma unroll
            for (int p = 0; p < 4; p++)
                ldmx4(bb[p], bufB + bRow + p * 8192 +
                              (((uint32_t)(ks * 32) + bK) ^ bSw));
#pragma unroll
            for (int mf = 0; mf < 2; mf++)
#pragma unroll
                for (int p = 0; p < 4; p++) {
                    mma16816(acc[mf][2 * p],     a[mf], bb[p][0], bb[p][1]);
                    mma16816(acc[mf][2 * p + 1], a[mf], bb[p][2], bb[p][3]);
                }
        }

        // ---- per-tile argmin epilogue ----
        const int n0w = t * 128 + wn * 64;
        float eq[16];
#pragma unroll
        for (int nf = 0; nf < 8; nf++)
#pragma unroll
            for (int j = 0; j < 2; j++)
                eq[nf * 2 + j] = esq_s[n0w + nf * 8 + (lane & 3) * 2 + j];
#pragma unroll
        for (int nf = 0; nf < 8; nf++)
#pragma unroll
            for (int j = 0; j < 2; j++) {
                const float e = eq[nf * 2 + j];
                const int idx = n0w + nf * 8 + (lane & 3) * 2 + j;
#pragma unroll
                for (int mf = 0; mf < 2; mf++)
#pragma unroll
                    for (int h = 0; h < 2; h++) {
                        float sc = e - acc[mf][nf][h * 2 + j];
                        int s = mf * 2 + h;
                        if (sc < bestv[s]) {
                            secv[s] = bestv[s]; bestv[s] = sc; besti[s] = idx;
                        } else if (sc < secv[s]) {
                            secv[s] = sc;
                        }
                    }
            }
        __syncthreads();
    }

    // ---- quad (lane%4) reduction via shfl ----
#pragma unroll
    for (int s = 0; s < 4; s++) {
#pragma unroll
        for (int off = 1; off < 4; off <<= 1) {
            float ob = __shfl_xor_sync(0xffffffffu, bestv[s], off);
            float os = __shfl_xor_sync(0xffffffffu, secv[s], off);
            int   oi = __shfl_xor_sync(0xffffffffu, besti[s], off);
            merge3(bestv[s], secv[s], besti[s], ob, os, oi);
        }
    }
    // ---- cross-warp (wn) merge via SMEM (reuse esq region) ----
    float* bR = esq_s;            // 256
    float* sR = esq_s + 256;      // 256
    int*   iR = (int*)(esq_s + 512);
    if ((lane & 3) == 0) {
#pragma unroll
        for (int s = 0; s < 4; s++) {
            int r = wm * 32 + (s >> 1) * 16 + (lane >> 2) + (s & 1) * 8;
            bR[wn * 128 + r] = bestv[s];
            sR[wn * 128 + r] = secv[s];
            iR[wn * 128 + r] = besti[s];
        }
    }
    __syncthreads();
    if (tid < 128) {
        float b = bR[tid], s = sR[tid];
        int   i = iR[tid];
        merge3(b, s, i, bR[128 + tid], sR[128 + tid], iR[128 + tid]);
        g_row_idx[row0 + tid] = i;
        if (s - b < TH1) {
            int p = atomicAdd(&g_nrisky, 1);
            if (p < RCAP) g_risky[p] = row0 + tid;
        }
    }
}

// ============================================================================
// Rescue: fp16-split 3-term GEMM on risky rows. 16 rows per CTA, full K.
// SMEM: A_hi 0..8K | A_lo 8K..16K | B 16K..144K (2 x [hi 32K | lo 32K]) | esq 144K..176K
// ============================================================================
#define R_AH 0u
#define R_AL 8192u
#define R_B  16384u
#define R_E  147456u
#define RES_SMEM 180224

__global__ __launch_bounds__(256, 1) void vq_rescue() {
    int count = g_nrisky; if (count > RCAP) count = RCAP;
    const int blk = blockIdx.x;
    if (blk * 16 >= count) return;

    extern __shared__ char sm[];
    const uint32_t sb = smem_u32(sm);
    float* esq_s = reinterpret_cast<float*>(sm + R_E);
    __shared__ int ridx_s[16];
    const int tid = threadIdx.x, lane = tid & 31, w = tid >> 5;

    if (tid < 16) {
        int gp = blk * 16 + tid;
        ridx_s[tid] = (gp < count) ? g_risky[gp] : g_risky[blk * 16];
    }
    __syncthreads();

    // prologue: A hi/lo, esq, B tile 0 -> group 0
#pragma unroll
    for (int q = 0; q < 2; q++) {
        int lin = q * 256 + tid;
        int r = lin >> 5, c = lin & 31;
        uint32_t swo = (uint32_t)r * 512 + ((c * 16) ^ ((r & 7) << 4));
        int gr = ridx_s[r];
        cp16(sb + R_AH + swo, g_z_hi + (size_t)gr * DDIM + c * 8);
        cp16(sb + R_AL + swo, g_z_lo + (size_t)gr * DDIM + c * 8);
    }
#pragma unroll
    for (int q = 0; q < 8; q++) {
        int c2 = q * 256 + tid;
        cp16(sb + R_E + c2 * 16, g_esq + c2 * 4);
    }
#pragma unroll
    for (int q = 0; q < 8; q++) {
        int lin = q * 256 + tid;
        int r = lin >> 5, c = lin & 31;
        uint32_t swo = (uint32_t)r * 512 + ((c * 16) ^ ((r & 7) << 4));
        cp16(sb + R_B + swo,         g_cb_hi + (size_t)r * DDIM + c * 8);
        cp16(sb + R_B + 32768 + swo, g_cb_lo + (size_t)r * DDIM + c * 8);
    }
    CPC();

    const uint32_t aRow = (uint32_t)(lane & 15) * 512;
    const uint32_t aK   = (uint32_t)((lane >> 4) * 16);
    const uint32_t aSw  = (uint32_t)((lane & 7) << 4);
    const uint32_t bRow = (uint32_t)(w * 8 + (lane & 7)) * 512;
    const uint32_t bK   = (uint32_t)(((lane >> 3) & 3) * 16);
    const uint32_t bSw  = aSw;

    float bestv[2], secv[2];
    int   besti[2];
#pragma unroll
    for (int s = 0; s < 2; s++) { bestv[s] = 3.4e38f; secv[s] = 3.4e38f; besti[s] = 0; }

    for (int t = 0; t < 128; t++) {
        if (t + 1 < 128) {
            const size_t nb = (size_t)(t + 1) * 64 * DDIM;
            uint32_t dstB = sb + R_B + (uint32_t)((t + 1) & 1) * 65536;
#pragma unroll
            for (int q = 0; q < 8; q++) {
                int lin = q * 256 + tid;
                int r = lin >> 5, c = lin & 31;
                uint32_t swo = (uint32_t)r * 512 + ((c * 16) ^ ((r & 7) << 4));
                cp16(dstB + swo,         g_cb_hi + nb + (size_t)r * DDIM + c * 8);
                cp16(dstB + 32768 + swo, g_cb_lo + nb + (size_t)r * DDIM + c * 8);
            }
            CPC();
            CPW(1);
        } else {
            CPW(0);
        }
        __syncthreads();

        const uint32_t bufHi = sb + R_B + (uint32_t)(t & 1) * 65536;
        const uint32_t bufLo = bufHi + 32768;
        float acc[4] = {0.f, 0.f, 0.f, 0.f};

#pragma unroll
        for (int ks2 = 0; ks2 < 8; ks2++) {
            uint32_t bh[4], bl[4];
            ldmx4(bh, bufHi + bRow + (((uint32_t)(ks2 * 64) + bK) ^ bSw));
            ldmx4(bl, bufLo + bRow + (((uint32_t)(ks2 * 64) + bK) ^ bSw));
#pragma unroll
            for (int sub = 0; sub < 2; sub++) {
                const int ks = ks2 * 2 + sub;
                uint32_t ah[4], al[4];
                ldmx4(ah, sb + R_AH + aRow + (((uint32_t)(ks * 32) + aK) ^ aSw));
                ldmx4(al, sb + R_AL + aRow + (((uint32_t)(ks * 32) + aK) ^ aSw));
                mma16816(acc, ah, bh[sub * 2], bh[sub * 2 + 1]);
                mma16816(acc, ah, bl[sub * 2], bl[sub * 2 + 1]);
                mma16816(acc, al, bh[sub * 2], bh[sub * 2 + 1]);
            }
        }

        const int n0 = t * 64 + w * 8;
#pragma unroll
        for (int j = 0; j < 2; j++) {
            const int idx = n0 + (lane & 3) * 2 + j;
            const float e = esq_s[idx];
#pragma unroll
            for (int h = 0; h < 2; h++) {
                float sc = e - acc[h * 2 + j];
                if (sc < bestv[h]) {
                    secv[h] = bestv[h]; bestv[h] = sc; besti[h] = idx;
                } else if (sc < secv[h]) {
                    secv[h] = sc;
                }
            }
        }
        __syncthreads();
    }

#pragma unroll
    for (int s = 0; s < 2; s++) {
#pragma unroll
        for (int off = 1; off < 4; off <<= 1) {
            float ob = __shfl_xor_sync(0xffffffffu, bestv[s], off);
            float os = __shfl_xor_sync(0xffffffffu, secv[s], off);
            int   oi = __shfl_xor_sync(0xffffffffu, besti[s], off);
            merge3(bestv[s], secv[s], besti[s], ob, os, oi);
        }
    }
    float* bR = esq_s;            // 128
    float* sR = esq_s + 128;
    int*   iR = (int*)(esq_s + 256);
    if ((lane & 3) == 0) {
#pragma unroll
        for (int s = 0; s < 2; s++) {
            int r = (lane >> 2) + s * 8;
            bR[w * 16 + r] = bestv[s];
            sR[w * 16 + r] = secv[s];
            iR[w * 16 + r] = besti[s];
        }
    }
    __syncthreads();
    if (tid < 16) {
        float b = bR[tid], s = sR[tid];
        int i = iR[tid];
#pragma unroll
        for (int w2 = 1; w2 < 8; w2++)
            merge3(b, s, i, bR[w2 * 16 + tid], sR[w2 * 16 + tid], iR[w2 * 16 + tid]);
        int gp = blk * 16 + tid;
        if (gp < count) {
            int grow = ridx_s[tid];
            g_row_idx[grow] = i;
            if (s - b < TH2) {
                int p = atomicAdd(&g_nr2, 1);
                if (p < R2CAP) g_r2[p] = grow;
            }
        }
    }
}

// ============================================================================
// Exact fp32 tail for near-tie rows
// ============================================================================
__global__ __launch_bounds__(256) void vq_exact(const float* __restrict__ z_e,
                                                const float* __restrict__ cb) {
    __shared__ float zs[DDIM];
    __shared__ float rv[256];
    __shared__ int   ri[256];
    const int tid = threadIdx.x;
    int n = g_nr2; if (n > R2CAP) n = R2CAP;
    for (int i = blockIdx.x; i < n; i += gridDim.x) {
        const int row = g_r2[i];
        zs[tid] = z_e[(size_t)row * DDIM + tid];
        __syncthreads();
        float bv = 3.4e38f; int bi = 0x7fffffff;
        const float4* z4 = reinterpret_cast<const float4*>(zs);
        for (int k = tid; k < KROWS; k += 256) {
            const float4* c4 = reinterpret_cast<const float4*>(cb + (size_t)k * DDIM);
            float dot = 0.f;
#pragma unroll
            for (int d = 0; d < DDIM / 4; d++) {
                float4 a = z4[d], e = c4[d];
                dot = fmaf(a.x, e.x, dot); dot = fmaf(a.y, e.y, dot);
                dot = fmaf(a.z, e.z, dot); dot = fmaf(a.w, e.w, dot);
            }
            float s = g_esq[k] - dot;
            if (s < bv || (s == bv && k < bi)) { bv = s; bi = k; }
        }
        rv[tid] = bv; ri[tid] = bi;
        __syncthreads();
#pragma unroll
        for (int st = 128; st > 0; st >>= 1) {
            if (tid < st) {
                float v2 = rv[tid + st]; int i2 = ri[tid + st];
                if (v2 < rv[tid] || (v2 == rv[tid] && i2 < ri[tid])) {
                    rv[tid] = v2; ri[tid] = i2;
                }
            }
            __syncthreads();
        }
        if (tid == 0) g_row_idx[row] = ri[0];
        __syncthreads();
    }
}

// ============================================================================
// Output epilogue + final loss
// ============================================================================
__global__ __launch_bounds__(256)
void out_kernel(const float* __restrict__ z_e, const float* __restrict__ cb,
                float* __restrict__ out, long long out_size) {
    __shared__ float red[256];
    const int tid = threadIdx.x;
    const int row0 = blockIdx.x * 128;
    float lsum = 0.f;
    for (int r = 0; r < 128; r++) {
        const int row = row0 + r;
        const int idx = g_row_idx[row];
        float ze = z_e[(size_t)row * DDIM + tid];
        float zq = cb[(size_t)idx * DDIM + tid];
        float d = zq - ze;
        long long pos = (long long)row * DDIM + tid;
        if (pos < out_size) out[pos] = ze + d;
        lsum += d * d;
    }
    if (tid < 128) {
        long long pos = (long long)BROWS * DDIM + row0 + tid;
        if (pos < out_size) out[pos] = (float)g_row_idx[row0 + tid];
    }
    red[tid] = lsum;
    __syncthreads();
#pragma unroll
    for (int st = 128; st > 0; st >>= 1) {
        if (tid < st) red[tid] += red[tid + st];
        __syncthreads();
    }
    if (tid == 0) g_partial[blockIdx.x] = red[0];
}

__global__ void final_kernel(float* __restrict__ out, long long out_size) {
    if (threadIdx.x == 0 && blockIdx.x == 0) {
        float s = 0.f;
        for (int i = 0; i < BROWS / 128; i++) s += g_partial[i];
        float mse = s / ((float)BROWS * (float)DDIM);
        long long pos = (long long)BROWS * DDIM + BROWS;
        if (pos < out_size) out[pos] = 1.25f * mse;
    }
}

// ============================================================================
extern "C" void kernel_launch(void* const* d_in, const int* in_sizes, int n_in,
                              void* d_out, int out_size) {
    const float* z_e = (const float*)d_in[0];
    const float* cb  = (const float*)d_in[1];
    float* out       = (float*)d_out;

    void *p_zhi, *p_zlo, *p_chi, *p_clo;
    cudaGetSymbolAddress(&p_zhi, g_z_hi);
    cudaGetSymbolAddress(&p_zlo, g_z_lo);
    cudaGetSymbolAddress(&p_chi, g_cb_hi);
    cudaGetSymbolAddress(&p_clo, g_cb_lo);

    init_kernel<<<1, 1>>>();
    split_kernel<<<(BROWS * DDIM / 4) / 256, 256>>>(
        z_e, (__half*)p_zhi, (__half*)p_zlo, BROWS * DDIM / 4);
    split_kernel<<<(KROWS * DDIM / 4) / 256, 256>>>(
        cb, (__half*)p_chi, (__half*)p_clo, KROWS * DDIM / 4);
    esq_kernel<<<KROWS / 8, 256>>>(cb);

    cudaFuncSetAttribute(vq_screen, cudaFuncAttributeMaxDynamicSharedMemorySize,
                         SCR_SMEM);
    vq_screen<<<BROWS / 128, 256, SCR_SMEM>>>();

    cudaFuncSetAttribute(vq_rescue, cudaFuncAttributeMaxDynamicSharedMemorySize,
                         RES_SMEM);
    vq_rescue<<<RCAP / 16, 256, RES_SMEM>>>();

    vq_exact<<<128, 256>>>(z_e, cb);
    out_kernel<<<BROWS / 128, 256>>>(z_e, cb, out, (long long)out_size);
    final_kernel<<<1, 32>>>(out, (long long)out_size);
}

// round 5
// speedup vs baseline: 3.4372x; 1.2739x over previous
#include <cuda_runtime.h>
#include <cuda_fp16.h>
#include <cstdint>

#define BROWS  32768
#define KROWS  8192
#define DDIM   256
#define TH1    0.06f
#define TH2    1e-3f
#define RCAP   8192
#define R2CAP  1024

// ---------------- device globals (no cudaMalloc allowed) --------------------
__device__ __align__(16) __half g_z_hi[BROWS * DDIM];
__device__ __align__(16) __half g_z_lo[BROWS * DDIM];
__device__ __align__(16) __half g_cb_hi[KROWS * DDIM];
__device__ __align__(16) __half g_cb_lo[KROWS * DDIM];
__device__ __align__(16) float g_esq[KROWS];
__device__ int   g_row_idx[BROWS];
__device__ int   g_nrisky;
__device__ int   g_risky[RCAP];
__device__ float g_rb[RCAP * 8];
__device__ float g_rs[RCAP * 8];
__device__ int   g_ri[RCAP * 8];
__device__ int   g_nr2;
__device__ int   g_r2[R2CAP];
__device__ float g_partial[BROWS / 128];

// ---------------- asm helpers (baseline PTX only) ----------------------------
__device__ __forceinline__ uint32_t smem_u32(const void* p) {
    uint32_t a;
    asm("{ .reg .u64 t; cvta.to.shared.u64 t, %1; cvt.u32.u64 %0, t; }"
        : "=r"(a) : "l"(p));
    return a;
}
__device__ __forceinline__ void ldmx4(uint32_t r[4], uint32_t addr) {
    asm volatile("ldmatrix.sync.aligned.m8n8.x4.shared.b16 {%0,%1,%2,%3}, [%4];\n"
        : "=r"(r[0]), "=r"(r[1]), "=r"(r[2]), "=r"(r[3]) : "r"(addr));
}
__device__ __forceinline__ void mma16816(float c[4], const uint32_t a[4],
                                         uint32_t b0, uint32_t b1) {
    asm volatile(
        "mma.sync.aligned.m16n8k16.row.col.f32.f16.f16.f32 "
        "{%0,%1,%2,%3}, {%4,%5,%6,%7}, {%8,%9}, {%0,%1,%2,%3};\n"
        : "+f"(c[0]), "+f"(c[1]), "+f"(c[2]), "+f"(c[3])
        : "r"(a[0]), "r"(a[1]), "r"(a[2]), "r"(a[3]), "r"(b0), "r"(b1));
}
__device__ __forceinline__ void cp16(uint32_t dst, const void* src) {
    asm volatile("cp.async.cg.shared.global [%0], [%1], 16;\n"
        :: "r"(dst), "l"(src));
}
#define CPC()  asm volatile("cp.async.commit_group;\n" ::: "memory")
#define CPW(n) asm volatile("cp.async.wait_group %0;\n" :: "n"(n) : "memory")

__device__ __forceinline__ void merge3(float& b, float& s, int& i,
                                       float ob, float os, int oi) {
    if (ob < b || (ob == b && oi < i)) {
        s = fminf(b, os); b = ob; i = oi;
    } else {
        s = fminf(s, ob);
    }
}

// ---------------- prep kernels ----------------------------------------------
__global__ void split_kernel(const float* __restrict__ src,
                             __half* __restrict__ hi,
                             __half* __restrict__ lo, int n4) {
    int i = blockIdx.x * blockDim.x + threadIdx.x;
    if (i >= n4) return;
    float4 v = reinterpret_cast<const float4*>(src)[i];
    __half h0 = __float2half(v.x), h1 = __float2half(v.y);
    __half h2 = __float2half(v.z), h3 = __float2half(v.w);
    __half2 hp0; hp0.x = h0; hp0.y = h1;
    __half2 hp1; hp1.x = h2; hp1.y = h3;
    __half2 lp0, lp1;
    lp0.x = __float2half(v.x - __half2float(h0));
    lp0.y = __float2half(v.y - __half2float(h1));
    lp1.x = __float2half(v.z - __half2float(h2));
    lp1.y = __float2half(v.w - __half2float(h3));
    reinterpret_cast<__half2*>(hi)[i * 2 + 0] = hp0;
    reinterpret_cast<__half2*>(hi)[i * 2 + 1] = hp1;
    reinterpret_cast<__half2*>(lo)[i * 2 + 0] = lp0;
    reinterpret_cast<__half2*>(lo)[i * 2 + 1] = lp1;
}

__global__ void esq_kernel(const float* __restrict__ cb) {
    if (blockIdx.x == 0 && threadIdx.x == 0) { g_nrisky = 0; g_nr2 = 0; }
    int row = blockIdx.x * 8 + (threadIdx.x >> 5);
    if (row >= KROWS) return;
    int lane = threadIdx.x & 31;
    const float4* p = reinterpret_cast<const float4*>(cb + (size_t)row * DDIM);
    float s = 0.f;
#pragma unroll
    for (int i = 0; i < 2; i++) {
        float4 v = p[lane + 32 * i];
        s += v.x * v.x + v.y * v.y + v.z * v.z + v.w * v.w;
    }
#pragma unroll
    for (int o = 16; o; o >>= 1) s += __shfl_down_sync(0xffffffffu, s, o);
    if (lane == 0) g_esq[row] = 0.5f * s;
}

// ============================================================================
// Screen: fp16 HMMA, 512 threads (16 warps = 4/SMSP), 128 rows x full K.
// SMEM: A 64K | B 2x64K | esq 2x512B | red 6K
// ============================================================================
#define S_A   0u
#define S_B   65536u
#define S_E   196608u
#define S_RED 197632u
#define SCR_SMEM 203776

__global__ __launch_bounds__(512, 1) void vq_screen(int blk0) {
    extern __shared__ char sm[];
    const uint32_t sb = smem_u32(sm);
    const int tid = threadIdx.x, lane = tid & 31, w = tid >> 5;
    const int wm = w & 3, wn = w >> 2;
    const int row0 = (blk0 + blockIdx.x) * 128;

    // ---- prologue: A (64KB), esq tile0, B tile0 -> group 0 ----
#pragma unroll
    for (int q = 0; q < 8; q++) {
        int lin = q * 512 + tid;
        int r = lin >> 5, c = lin & 31;
        cp16(sb + S_A + r * 512 + ((c * 16) ^ ((r & 7) << 4)),
             g_z_hi + (size_t)(row0 + r) * DDIM + c * 8);
    }
    if (tid < 32) cp16(sb + S_E + tid * 16, g_esq + tid * 4);
#pragma unroll
    for (int q = 0; q < 8; q++) {
        int lin = q * 512 + tid;
        int r = lin >> 5, c = lin & 31;
        cp16(sb + S_B + r * 512 + ((c * 16) ^ ((r & 7) << 4)),
             g_cb_hi + (size_t)r * DDIM + c * 8);
    }
    CPC();

    const uint32_t aRow = (uint32_t)(wm * 32 + (lane & 15)) * 512;
    const uint32_t aK   = (uint32_t)((lane >> 4) * 16);
    const uint32_t aSw  = (uint32_t)((lane & 7) << 4);
    const uint32_t bRow = (uint32_t)(wn * 32 + (lane & 7) + ((lane >> 4) & 1) * 8) * 512;
    const uint32_t bK   = (uint32_t)(((lane >> 3) & 1) * 16);

    float bestv[4], secv[4];
    int   besti[4];
#pragma unroll
    for (int s = 0; s < 4; s++) { bestv[s] = 3.4e38f; secv[s] = 3.4e38f; besti[s] = 0; }

    for (int t = 0; t < 64; t++) {
        if (t + 1 < 64) {
            const __half* src = g_cb_hi + (size_t)(t + 1) * 128 * DDIM;
            uint32_t dstB = sb + S_B + (uint32_t)((t + 1) & 1) * 65536;
#pragma unroll
            for (int q = 0; q < 8; q++) {
                int lin = q * 512 + tid;
                int r = lin >> 5, c = lin & 31;
                cp16(dstB + r * 512 + ((c * 16) ^ ((r & 7) << 4)),
                     src + (size_t)r * DDIM + c * 8);
            }
            if (tid < 32)
                cp16(sb + S_E + (uint32_t)((t + 1) & 1) * 512 + tid * 16,
                     g_esq + (t + 1) * 128 + tid * 4);
            CPC();
            CPW(1);
        } else {
            CPW(0);
        }
        __syncthreads();

        const uint32_t bufB = sb + S_B + (uint32_t)(t & 1) * 65536;
        float acc[2][4][4];
#pragma unroll
        for (int mf = 0; mf < 2; mf++)
#pragma unroll
            for (int nf = 0; nf < 4; nf++)
#pragma unroll
                for (int k = 0; k < 4; k++) acc[mf][nf][k] = 0.f;

#pragma unroll
        for (int ks = 0; ks < 16; ks++) {
            uint32_t a[2][4];
#pragma unroll
            for (int mf = 0; mf < 2; mf++)
                ldmx4(a[mf], sb + S_A + aRow + mf * 8192 +
                              (((uint32_t)(ks * 32) + aK) ^ aSw));
            uint32_t bb[2][4];
#pragma unroll
            for (int p = 0; p < 2; p++)
                ldmx4(bb[p], bufB + bRow + p * 8192 +
                              (((uint32_t)(ks * 32) + bK) ^ aSw));
#pragma unroll
            for (int mf = 0; mf < 2; mf++)
#pragma unroll
                for (int p = 0; p < 2; p++) {
                    mma16816(acc[mf][2 * p],     a[mf], bb[p][0], bb[p][1]);
                    mma16816(acc[mf][2 * p + 1], a[mf], bb[p][2], bb[p][3]);
                }
        }

        // ---- per-tile argmin epilogue ----
        const float* esq_t = reinterpret_cast<const float*>(sm + S_E + (t & 1) * 512);
#pragma unroll
        for (int nf = 0; nf < 4; nf++)
#pragma unroll
            for (int j = 0; j < 2; j++) {
                const int col = wn * 32 + nf * 8 + (lane & 3) * 2 + j;
                const float e = esq_t[col];
                const int idx = t * 128 + col;
#pragma unroll
                for (int mf = 0; mf < 2; mf++)
#pragma unroll
                    for (int h = 0; h < 2; h++) {
                        float sc = e - acc[mf][nf][h * 2 + j];
                        int s = mf * 2 + h;
                        if (sc < bestv[s]) {
                            secv[s] = bestv[s]; bestv[s] = sc; besti[s] = idx;
                        } else if (sc < secv[s]) {
                            secv[s] = sc;
                        }
                    }
            }
        __syncthreads();
    }

    // ---- quad reduction ----
#pragma unroll
    for (int s = 0; s < 4; s++) {
#pragma unroll
        for (int off = 1; off < 4; off <<= 1) {
            float ob = __shfl_xor_sync(0xffffffffu, bestv[s], off);
            float os = __shfl_xor_sync(0xffffffffu, secv[s], off);
            int   oi = __shfl_xor_sync(0xffffffffu, besti[s], off);
            merge3(bestv[s], secv[s], besti[s], ob, os, oi);
        }
    }
    // ---- cross-warp merge over wn (4 groups) ----
    float* bR = reinterpret_cast<float*>(sm + S_RED);
    float* sR = bR + 512;
    int*   iR = reinterpret_cast<int*>(bR + 1024);
    if ((lane & 3) == 0) {
#pragma unroll
        for (int s = 0; s < 4; s++) {
            int r = wm * 32 + (s >> 1) * 16 + (lane >> 2) + (s & 1) * 8;
            bR[wn * 128 + r] = bestv[s];
            sR[wn * 128 + r] = secv[s];
            iR[wn * 128 + r] = besti[s];
        }
    }
    __syncthreads();
    if (tid < 128) {
        float b = bR[tid], s = sR[tid];
        int   i = iR[tid];
#pragma unroll
        for (int g2 = 1; g2 < 4; g2++)
            merge3(b, s, i, bR[g2 * 128 + tid], sR[g2 * 128 + tid], iR[g2 * 128 + tid]);
        g_row_idx[row0 + tid] = i;
        if (s - b < TH1) {
            int p = atomicAdd(&g_nrisky, 1);
            if (p < RCAP) g_risky[p] = row0 + tid;
        }
    }
}

// ============================================================================
// Rescue: fp16 3-term split. 32 risky rows x 1024-code slice per CTA.
// grid = (RCAP/32, 8). SMEM: Ahi 16K | Alo 16K | B 2x64K | esq 2x256 | red
// ============================================================================
#define R_AH  0u
#define R_AL  16384u
#define R_B   32768u
#define R_E   163840u
#define R_RED 164352u
#define RES_SMEM 165888

__global__ __launch_bounds__(256, 1) void vq_rescue() {
    int count = g_nrisky; if (count > RCAP) count = RCAP;
    if ((int)blockIdx.x * 32 >= count) return;

    extern __shared__ char sm[];
    const uint32_t sb = smem_u32(sm);
    __shared__ int ridx_s[32];
    const int tid = threadIdx.x, lane = tid & 31, w = tid >> 5;
    const int mm = w & 1, nn = w >> 1;
    const int slice = blockIdx.y;
    const int code0 = slice * 1024;

    if (tid < 32) {
        int gp = blockIdx.x * 32 + tid;
        ridx_s[tid] = (gp < count) ? g_risky[gp] : g_risky[blockIdx.x * 32];
    }
    __syncthreads();

    // prologue: A hi/lo (32 rows), esq tile0, B tile0
#pragma unroll
    for (int q = 0; q < 4; q++) {
        int lin = q * 256 + tid;
        int r = lin >> 5, c = lin & 31;
        uint32_t swo = (uint32_t)r * 512 + ((c * 16) ^ ((r & 7) << 4));
        int gr = ridx_s[r];
        cp16(sb + R_AH + swo, g_z_hi + (size_t)gr * DDIM + c * 8);
        cp16(sb + R_AL + swo, g_z_lo + (size_t)gr * DDIM + c * 8);
    }
    if (tid < 16) cp16(sb + R_E + tid * 16, g_esq + code0 + tid * 4);
#pragma unroll
    for (int q = 0; q < 8; q++) {
        int lin = q * 256 + tid;
        int r = lin >> 5, c = lin & 31;
        uint32_t swo = (uint32_t)r * 512 + ((c * 16) ^ ((r & 7) << 4));
        cp16(sb + R_B + swo,         g_cb_hi + (size_t)(code0 + r) * DDIM + c * 8);
        cp16(sb + R_B + 32768 + swo, g_cb_lo + (size_t)(code0 + r) * DDIM + c * 8);
    }
    CPC();

    const uint32_t aRow = (uint32_t)(mm * 16 + (lane & 15)) * 512;
    const uint32_t aK   = (uint32_t)((lane >> 4) * 16);
    const uint32_t aSw  = (uint32_t)((lane & 7) << 4);
    const uint32_t bRow = (uint32_t)(nn * 16 + (lane & 7) + ((lane >> 4) & 1) * 8) * 512;
    const uint32_t bK   = (uint32_t)(((lane >> 3) & 1) * 16);

    float bestv[2], secv[2];
    int   besti[2];
#pragma unroll
    for (int s = 0; s < 2; s++) { bestv[s] = 3.4e38f; secv[s] = 3.4e38f; besti[s] = 0; }

    for (int t = 0; t < 16; t++) {
        if (t + 1 < 16) {
            const int cnext = code0 + (t + 1) * 64;
            uint32_t dstB = sb + R_B + (uint32_t)((t + 1) & 1) * 65536;
#pragma unroll
            for (int q = 0; q < 8; q++) {
                int lin = q * 256 + tid;
                int r = lin >> 5, c = lin & 31;
                uint32_t swo = (uint32_t)r * 512 + ((c * 16) ^ ((r & 7) << 4));
                cp16(dstB + swo,         g_cb_hi + (size_t)(cnext + r) * DDIM + c * 8);
                cp16(dstB + 32768 + swo, g_cb_lo + (size_t)(cnext + r) * DDIM + c * 8);
            }
            if (tid < 16)
                cp16(sb + R_E + (uint32_t)((t + 1) & 1) * 256 + tid * 16,
                     g_esq + cnext + tid * 4);
            CPC();
            CPW(1);
        } else {
            CPW(0);
        }
        __syncthreads();

        const uint32_t bufHi = sb + R_B + (uint32_t)(t & 1) * 65536;
        const uint32_t bufLo = bufHi + 32768;
        float acc[2][4];
#pragma unroll
        for (int nf = 0; nf < 2; nf++)
#pragma unroll
            for (int k = 0; k < 4; k++) acc[nf][k] = 0.f;

#pragma unroll
        for (int ks = 0; ks < 16; ks++) {
            uint32_t ah[4], al[4], bh[4], bl[4];
            ldmx4(ah, sb + R_AH + aRow + (((uint32_t)(ks * 32) + aK) ^ aSw));
            ldmx4(al, sb + R_AL + aRow + (((uint32_t)(ks * 32) + aK) ^ aSw));
            ldmx4(bh, bufHi + bRow + (((uint32_t)(ks * 32) + bK) ^ aSw));
            ldmx4(bl, bufLo + bRow + (((uint32_t)(ks * 32) + bK) ^ aSw));
            mma16816(acc[0], ah, bh[0], bh[1]);
            mma16816(acc[1], ah, bh[2], bh[3]);
            mma16816(acc[0], ah, bl[0], bl[1]);
            mma16816(acc[1], ah, bl[2], bl[3]);
            mma16816(acc[0], al, bh[0], bh[1]);
            mma16816(acc[1], al, bh[2], bh[3]);
        }

        const float* esq_t = reinterpret_cast<const float*>(sm + R_E + (t & 1) * 256);
#pragma unroll
        for (int nf = 0; nf < 2; nf++)
#pragma unroll
            for (int j = 0; j < 2; j++) {
                const int col = nn * 16 + nf * 8 + (lane & 3) * 2 + j;
                const float e = esq_t[col];
                const int idx = code0 + t * 64 + col;
#pragma unroll
                for (int h = 0; h < 2; h++) {
                    float sc = e - acc[nf][h * 2 + j];
                    if (sc < bestv[h]) {
                        secv[h] = bestv[h]; bestv[h] = sc; besti[h] = idx;
                    } else if (sc < secv[h]) {
                        secv[h] = sc;
                    }
                }
            }
        __syncthreads();
    }

#pragma unroll
    for (int s = 0; s < 2; s++) {
#pragma unroll
        for (int off = 1; off < 4; off <<= 1) {
            float ob = __shfl_xor_sync(0xffffffffu, bestv[s], off);
            float os = __shfl_xor_sync(0xffffffffu, secv[s], off);
            int   oi = __shfl_xor_sync(0xffffffffu, besti[s], off);
            merge3(bestv[s], secv[s], besti[s], ob, os, oi);
        }
    }
    float* bR = reinterpret_cast<float*>(sm + R_RED);
    float* sR = bR + 128;
    int*   iR = reinterpret_cast<int*>(bR + 256);
    if ((lane & 3) == 0) {
#pragma unroll
        for (int s = 0; s < 2; s++) {
            int r = mm * 16 + (lane >> 2) + s * 8;
            bR[nn * 32 + r] = bestv[s];
            sR[nn * 32 + r] = secv[s];
            iR[nn * 32 + r] = besti[s];
        }
    }
    __syncthreads();
    if (tid < 32) {
        float b = bR[tid], s = sR[tid];
        int   i = iR[tid];
#pragma unroll
        for (int g2 = 1; g2 < 4; g2++)
            merge3(b, s, i, bR[g2 * 32 + tid], sR[g2 * 32 + tid], iR[g2 * 32 + tid]);
        int slot = blockIdx.x * 32 + tid;
        if (slot < count) {
            g_rb[slot * 8 + slice] = b;
            g_rs[slot * 8 + slice] = s;
            g_ri[slot * 8 + slice] = i;
        }
    }
}

// merge 8 slices per risky slot
__global__ __launch_bounds__(256) void vq_merge() {
    int count = g_nrisky; if (count > RCAP) count = RCAP;
    int slot = blockIdx.x * 256 + threadIdx.x;
    if (slot >= count) return;
    float b = g_rb[slot * 8], s = g_rs[slot * 8];
    int   i = g_ri[slot * 8];
#pragma unroll
    for (int sl = 1; sl < 8; sl++)
        merge3(b, s, i, g_rb[slot * 8 + sl], g_rs[slot * 8 + sl], g_ri[slot * 8 + sl]);
    int row = g_risky[slot];
    g_row_idx[row] = i;
    if (s - b < TH2) {
        int p = atomicAdd(&g_nr2, 1);
        if (p < R2CAP) g_r2[p] = row;
    }
}

// ============================================================================
// Exact fp32 tail for near-tie rows
// ============================================================================
__global__ __launch_bounds__(256) void vq_exact(const float* __restrict__ z_e,
                                                const float* __restrict__ cb) {
    __shared__ float zs[DDIM];
    __shared__ float rv[256];
    __shared__ int   ri[256];
    const int tid = threadIdx.x;
    int n = g_nr2; if (n > R2CAP) n = R2CAP;
    for (int i = blockIdx.x; i < n; i += gridDim.x) {
        const int row = g_r2[i];
        zs[tid] = z_e[(size_t)row * DDIM + tid];
        __syncthreads();
        float bv = 3.4e38f; int bi = 0x7fffffff;
        const float4* z4 = reinterpret_cast<const float4*>(zs);
        for (int k = tid; k < KROWS; k += 256) {
            const float4* c4 = reinterpret_cast<const float4*>(cb + (size_t)k * DDIM);
            float dot = 0.f;
#pragma unroll
            for (int d = 0; d < DDIM / 4; d++) {
                float4 a = z4[d], e = c4[d];
                dot = fmaf(a.x, e.x, dot); dot = fmaf(a.y, e.y, dot);
                dot = fmaf(a.z, e.z, dot); dot = fmaf(a.w, e.w, dot);
            }
            float s = g_esq[k] - dot;
            if (s < bv || (s == bv && k < bi)) { bv = s; bi = k; }
        }
        rv[tid] = bv; ri[tid] = bi;
        __syncthreads();
#pragma unroll
        for (int st = 128; st > 0; st >>= 1) {
            if (tid < st) {
                float v2 = rv[tid + st]; int i2 = ri[tid + st];
                if (v2 < rv[tid] || (v2 == rv[tid] && i2 < ri[tid])) {
                    rv[tid] = v2; ri[tid] = i2;
                }
            }
            __syncthreads();
        }
        if (tid == 0) g_row_idx[row] = ri[0];
        __syncthreads();
    }
}

// ============================================================================
// Output epilogue + final loss
// ============================================================================
__global__ __launch_bounds__(256)
void out_kernel(const float* __restrict__ z_e, const float* __restrict__ cb,
                float* __restrict__ out, long long out_size) {
    __shared__ float red[256];
    const int tid = threadIdx.x;
    const int row0 = blockIdx.x * 128;
    float lsum = 0.f;
    for (int r = 0; r < 128; r++) {
        const int row = row0 + r;
        const int idx = g_row_idx[row];
        float ze = z_e[(size_t)row * DDIM + tid];
        float zq = cb[(size_t)idx * DDIM + tid];
        float d = zq - ze;
        long long pos = (long long)row * DDIM + tid;
        if (pos < out_size) out[pos] = ze + d;
        lsum += d * d;
    }
    if (tid < 128) {
        long long pos = (long long)BROWS * DDIM + row0 + tid;
        if (pos < out_size) out[pos] = (float)g_row_idx[row0 + tid];
    }
    red[tid] = lsum;
    __syncthreads();
#pragma unroll
    for (int st = 128; st > 0; st >>= 1) {
        if (tid < st) red[tid] += red[tid + st];
        __syncthreads();
    }
    if (tid == 0) g_partial[blockIdx.x] = red[0];
}

__global__ void final_kernel(float* __restrict__ out, long long out_size) {
    if (threadIdx.x == 0 && blockIdx.x == 0) {
        float s = 0.f;
        for (int i = 0; i < BROWS / 128; i++) s += g_partial[i];
        float mse = s / ((float)BROWS * (float)DDIM);
        long long pos = (long long)BROWS * DDIM + BROWS;
        if (pos < out_size) out[pos] = 1.25f * mse;
    }
}

// ============================================================================
extern "C" void kernel_launch(void* const* d_in, const int* in_sizes, int n_in,
                              void* d_out, int out_size) {
    const float* z_e = (const float*)d_in[0];
    const float* cb  = (const float*)d_in[1];
    float* out       = (float*)d_out;

    void *p_zhi, *p_zlo, *p_chi, *p_clo;
    cudaGetSymbolAddress(&p_zhi, g_z_hi);
    cudaGetSymbolAddress(&p_zlo, g_z_lo);
    cudaGetSymbolAddress(&p_chi, g_cb_hi);
    cudaGetSymbolAddress(&p_clo, g_cb_lo);

    split_kernel<<<(BROWS * DDIM / 4) / 256, 256>>>(
        z_e, (__half*)p_zhi, (__half*)p_zlo, BROWS * DDIM / 4);
    split_kernel<<<(KROWS * DDIM / 4) / 256, 256>>>(
        cb, (__half*)p_chi, (__half*)p_clo, KROWS * DDIM / 4);
    esq_kernel<<<KROWS / 8, 256>>>(cb);

    cudaFuncSetAttribute(vq_screen, cudaFuncAttributeMaxDynamicSharedMemorySize,
                         SCR_SMEM);
    vq_screen<<<128, 512, SCR_SMEM>>>(0);
    vq_screen<<<128, 512, SCR_SMEM>>>(128);

    cudaFuncSetAttribute(vq_rescue, cudaFuncAttributeMaxDynamicSharedMemorySize,
                         RES_SMEM);
    dim3 rg(RCAP / 32, 8);
    vq_rescue<<<rg, 256, RES_SMEM>>>();
    vq_merge<<<RCAP / 256, 256>>>();

    vq_exact<<<128, 256>>>(z_e, cb);
    out_kernel<<<BROWS / 128, 256>>>(z_e, cb, out, (long long)out_size);
    final_kernel<<<1, 32>>>(out, (long long)out_size);
}